// round 11
// baseline (speedup 1.0000x reference)
#include <cuda_runtime.h>
#include <cstdint>

typedef unsigned long long u64;

#define B_    256
#define T_    512
#define NPAIR 128

// ---- device scratch (no allocations allowed) ------------------------------
__device__ __align__(16) float  g_seqA[(size_t)T_ * B_ * 64];   // 33.5 MB [t][b][64]
__device__ __align__(16) float4 g_pb0[(size_t)T_ * B_];         // 2 MB    [t*256+b]

// ---- packed f32x2 helpers -------------------------------------------------
__device__ __forceinline__ u64 pk2(float a, float b) {
    u64 r; asm("mov.b64 %0, {%1, %2};" : "=l"(r) : "f"(a), "f"(b)); return r;
}
__device__ __forceinline__ void unpk(u64 v, float& a, float& b) {
    asm("mov.b64 {%0, %1}, %2;" : "=f"(a), "=f"(b) : "l"(v));
}
__device__ __forceinline__ u64 ffma2(u64 a, u64 b, u64 c) {
    u64 d; asm("fma.rn.f32x2 %0, %1, %2, %3;" : "=l"(d) : "l"(a), "l"(b), "l"(c)); return d;
}

// ---- fast activations (MUFU ex2+rcp, ~1e-7 err) ---------------------------
#define L2E 1.4426950408889634f
__device__ __forceinline__ float ex2a(float x) {
    float r; asm("ex2.approx.ftz.f32 %0, %1;" : "=f"(r) : "f"(x)); return r;
}
__device__ __forceinline__ float rcpa(float x) {
    float r; asm("rcp.approx.ftz.f32 %0, %1;" : "=f"(r) : "f"(x)); return r;
}
__device__ __forceinline__ float tna(float x) {
    return fmaf(-2.f, rcpa(1.f + ex2a(2.f * L2E * x)), 1.f);
}

// ---- fused a0+a1+a2 pipeline: quad-gate lanes, ONE barrier/step ------------
// (unchanged from round 10 — passing at 940us, protected)
#define SMEM_FUSE_BYTES 138240

__global__ __launch_bounds__(256, 1) void fuseA(
    const float* __restrict__ x,
    const float* __restrict__ wih_a0, const float* __restrict__ whh_a0,
    const float* __restrict__ bih_a0, const float* __restrict__ bhh_a0,
    const float* __restrict__ wih_a1, const float* __restrict__ whh_a1,
    const float* __restrict__ bih_a1, const float* __restrict__ bhh_a1,
    const float* __restrict__ wih_a2, const float* __restrict__ whh_a2,
    const float* __restrict__ bih_a2, const float* __restrict__ bhh_a2)
{
    extern __shared__ __align__(16) char smem[];
    ulonglong2* wT2 = reinterpret_cast<ulonglong2*>(smem);
    ulonglong2* wT3 = reinterpret_cast<ulonglong2*>(smem + 65536);
    float*  xs  = reinterpret_cast<float*>(smem + 131072);   // [2][512]
    float*  hs  = reinterpret_cast<float*>(smem + 135168);   // [2][3][2][64]

    const int tid  = threadIdx.x;
    const int lane = tid & 31, w = tid >> 5;
    const int gt   = lane & 3;                 // 0=i 1=f 2=g 3=o
    const int u    = w * 8 + (lane >> 2);      // unit 0..63
    const int gq   = gt * 64 + u;              // gate row index
    const bool isF = (gt == 1);
    const int pair = blockIdx.x;

    u64 wr0[32], wr1[32], wr2[32];
    {
        const u64* p0 = reinterpret_cast<const u64*>(whh_a0) + (size_t)gq * 32;
        const u64* p1 = reinterpret_cast<const u64*>(wih_a1) + (size_t)gq * 32;
        const u64* p2 = reinterpret_cast<const u64*>(whh_a1) + (size_t)gq * 32;
#pragma unroll
        for (int j = 0; j < 32; ++j) {
            wr0[j] = __ldg(p0 + j);
            wr1[j] = __ldg(p1 + j);
            wr2[j] = __ldg(p2 + j);
        }
    }
    {
        const ulonglong2* p2 = reinterpret_cast<const ulonglong2*>(wih_a2) + (size_t)gq * 16;
        const ulonglong2* p3 = reinterpret_cast<const ulonglong2*>(whh_a2) + (size_t)gq * 16;
#pragma unroll 4
        for (int i = 0; i < 16; ++i) {
            wT2[i * 256 + tid] = __ldg(p2 + i);
            wT3[i * 256 + tid] = __ldg(p3 + i);
        }
    }
#pragma unroll 2
    for (int k = 0; k < 4; ++k) {
        int i = tid + 256 * k, bl = i >> 9, t = i & 511;
        xs[bl * 512 + t] = x[(size_t)(pair * 2 + bl) * T_ + t];
    }
    if (tid < 128) {
#pragma unroll 2
        for (int q = 0; q < 6; ++q) hs[q * 128 + tid] = 0.f;
    }

    const float bias0 = __ldg(bih_a0 + gq) + __ldg(bhh_a0 + gq);
    const float bias1 = __ldg(bih_a1 + gq) + __ldg(bhh_a1 + gq);
    const float bias2 = __ldg(bih_a2 + gq) + __ldg(bhh_a2 + gq);
    const float wx0   = __ldg(wih_a0 + gq);

    const bool istanh = (gt == 2);
    const float ca = istanh ? 2.f * L2E : -L2E;
    const float aa = istanh ? 1.f : 0.f;
    const float bm = istanh ? -2.f : 1.f;

    float c0a = 0.f, c0b = 0.f, c1a = 0.f, c1b = 0.f, c2a = 0.f, c2b = 0.f;
    int p = 0;
    __syncthreads();

#pragma unroll 1
    for (int s = 0; s < T_ + 2; ++s) {
        const bool L0 = (s < T_);
        const bool L1 = (s >= 1) & (s < T_ + 1);
        const bool L2 = (s >= 2);
        const float* hb = hs + p * 384;
        float* hw = hs + (p ^ 1) * 384;

        float v0a = 0.f, v0b = 0.f, p1a = 0.f, p1b = 0.f;
        float h1a = 0.f, h1b = 0.f, p2a = 0.f, p2b = 0.f;
        float h2a = 0.f, h2b = 0.f;

        if (L0 | L1) {
            const ulonglong2* q0p = reinterpret_cast<const ulonglong2*>(hb + 0);
            const ulonglong2* q1p = reinterpret_cast<const ulonglong2*>(hb + 64);
            u64 ax = 0, bx = 0, ix = 0, jx = 0;
#pragma unroll
            for (int i = 0; i < 16; ++i) {
                ulonglong2 q0 = q0p[i], q1 = q1p[i];
                ax = ffma2(wr0[2 * i], q0.x, ax); ax = ffma2(wr0[2 * i + 1], q0.y, ax);
                bx = ffma2(wr0[2 * i], q1.x, bx); bx = ffma2(wr0[2 * i + 1], q1.y, bx);
                ix = ffma2(wr1[2 * i], q0.x, ix); ix = ffma2(wr1[2 * i + 1], q0.y, ix);
                jx = ffma2(wr1[2 * i], q1.x, jx); jx = ffma2(wr1[2 * i + 1], q1.y, jx);
            }
            float e, o;
            unpk(ax, e, o); v0a = e + o;
            unpk(bx, e, o); v0b = e + o;
            unpk(ix, e, o); p1a = e + o;
            unpk(jx, e, o); p1b = e + o;
        }
        if (L1 | L2) {
            const ulonglong2* q0p = reinterpret_cast<const ulonglong2*>(hb + 128);
            const ulonglong2* q1p = reinterpret_cast<const ulonglong2*>(hb + 192);
            u64 ax = 0, bx = 0, ix = 0, jx = 0;
#pragma unroll
            for (int i = 0; i < 16; ++i) {
                ulonglong2 q0 = q0p[i], q1 = q1p[i];
                ulonglong2 wv = wT2[i * 256 + tid];
                ax = ffma2(wr2[2 * i], q0.x, ax); ax = ffma2(wr2[2 * i + 1], q0.y, ax);
                bx = ffma2(wr2[2 * i], q1.x, bx); bx = ffma2(wr2[2 * i + 1], q1.y, bx);
                ix = ffma2(wv.x, q0.x, ix);       ix = ffma2(wv.y, q0.y, ix);
                jx = ffma2(wv.x, q1.x, jx);       jx = ffma2(wv.y, q1.y, jx);
            }
            float e, o;
            unpk(ax, e, o); h1a = e + o;
            unpk(bx, e, o); h1b = e + o;
            unpk(ix, e, o); p2a = e + o;
            unpk(jx, e, o); p2b = e + o;
        }
        if (L2) {
            const ulonglong2* q0p = reinterpret_cast<const ulonglong2*>(hb + 256);
            const ulonglong2* q1p = reinterpret_cast<const ulonglong2*>(hb + 320);
            u64 ax = 0, bx = 0;
#pragma unroll
            for (int i = 0; i < 16; ++i) {
                ulonglong2 q0 = q0p[i], q1 = q1p[i];
                ulonglong2 wv = wT3[i * 256 + tid];
                ax = ffma2(wv.x, q0.x, ax); ax = ffma2(wv.y, q0.y, ax);
                bx = ffma2(wv.x, q1.x, bx); bx = ffma2(wv.y, q1.y, bx);
            }
            float e, o;
            unpk(ax, e, o); h2a = e + o;
            unpk(bx, e, o); h2b = e + o;
        }

        if (L0) {
            float va = v0a + fmaf(wx0, xs[s], bias0);
            float vb = v0b + fmaf(wx0, xs[512 + s], bias0);
            float ra = fmaf(bm, rcpa(1.f + ex2a(ca * va)), aa);
            float rb = fmaf(bm, rcpa(1.f + ex2a(ca * vb)), aa);
            float r2a = __shfl_xor_sync(0xffffffffu, ra, 2);
            float r2b = __shfl_xor_sync(0xffffffffu, rb, 2);
            float r1a = __shfl_xor_sync(0xffffffffu, ra * r2a, 1);
            float r1b = __shfl_xor_sync(0xffffffffu, rb * r2b, 1);
            if (isF) {
                c0a = fmaf(ra, c0a, r1a);
                c0b = fmaf(rb, c0b, r1b);
                hw[u]      = r2a * tna(c0a);
                hw[64 + u] = r2b * tna(c0b);
            }
        }
        if (L1) {
            float va = h1a + p1a + bias1;
            float vb = h1b + p1b + bias1;
            float ra = fmaf(bm, rcpa(1.f + ex2a(ca * va)), aa);
            float rb = fmaf(bm, rcpa(1.f + ex2a(ca * vb)), aa);
            float r2a = __shfl_xor_sync(0xffffffffu, ra, 2);
            float r2b = __shfl_xor_sync(0xffffffffu, rb, 2);
            float r1a = __shfl_xor_sync(0xffffffffu, ra * r2a, 1);
            float r1b = __shfl_xor_sync(0xffffffffu, rb * r2b, 1);
            if (isF) {
                c1a = fmaf(ra, c1a, r1a);
                c1b = fmaf(rb, c1b, r1b);
                hw[128 + u] = r2a * tna(c1a);
                hw[192 + u] = r2b * tna(c1b);
            }
        }
        if (L2) {
            float va = h2a + p2a + bias2;
            float vb = h2b + p2b + bias2;
            float ra = fmaf(bm, rcpa(1.f + ex2a(ca * va)), aa);
            float rb = fmaf(bm, rcpa(1.f + ex2a(ca * vb)), aa);
            float r2a = __shfl_xor_sync(0xffffffffu, ra, 2);
            float r2b = __shfl_xor_sync(0xffffffffu, rb, 2);
            float r1a = __shfl_xor_sync(0xffffffffu, ra * r2a, 1);
            float r1b = __shfl_xor_sync(0xffffffffu, rb * r2b, 1);
            if (isF) {
                c2a = fmaf(ra, c2a, r1a);
                c2b = fmaf(rb, c2b, r1b);
                float ha = r2a * tna(c2a);
                float hb2 = r2b * tna(c2b);
                hw[256 + u] = ha;
                hw[320 + u] = hb2;
                g_seqA[((size_t)(s - 2) * B_ + pair * 2 + 0) * 64 + u] = ha;
                g_seqA[((size_t)(s - 2) * B_ + pair * 2 + 1) * 64 + u] = hb2;
            }
        }
        __syncthreads();
        p ^= 1;
    }
}

// ---------------------------------------------------------------------------
// b0 pre-gates: g_pb0[t*256+b] = bias_b0 + W_ih_b0[4,64] . seqA[t][b]
// ---------------------------------------------------------------------------
__global__ __launch_bounds__(256, 1) void preb0(
    const float* __restrict__ w_ih, const float* __restrict__ b_ih,
    const float* __restrict__ b_hh)
{
    __shared__ u64 wsm[128];
    __shared__ float bsm[4];
    const int tid = threadIdx.x;
    if (tid < 128) wsm[tid] = __ldg(reinterpret_cast<const u64*>(w_ih) + tid);
    if (tid < 4) bsm[tid] = __ldg(b_ih + tid) + __ldg(b_hh + tid);
    __syncthreads();

    const size_t slot = (size_t)blockIdx.x * 256 + tid;  // = t*256 + b
    const u64* xp = reinterpret_cast<const u64*>(g_seqA) + slot * 32;
    u64 acc[4] = {0ull, 0ull, 0ull, 0ull};
#pragma unroll 8
    for (int j = 0; j < 32; ++j) {
        u64 xv = __ldg(xp + j);
#pragma unroll
        for (int gg = 0; gg < 4; ++gg)
            acc[gg] = ffma2(wsm[gg * 32 + j], xv, acc[gg]);
    }
    float r[4];
#pragma unroll
    for (int gg = 0; gg < 4; ++gg) {
        float e, o; unpk(acc[gg], e, o);
        r[gg] = e + o + bsm[gg];
    }
    g_pb0[slot] = make_float4(r[0], r[1], r[2], r[3]);
}

// ---------------------------------------------------------------------------
// b0,b1,b2 scalar recurrences: quad-gate lanes (gt=i,f,g,o), layer-pipelined.
// 32 blocks x 32 threads; lane l -> chain b = blk*8 + (l>>2), gate gt = l&3.
// Cell update: shfl_xor(2) pairs i<->g, f<->o; shfl_xor(1) sends
// sig(i)*tanh(g) to the f-lane; f-lane owns c; h broadcast via shfl.
// ---------------------------------------------------------------------------
__global__ __launch_bounds__(32, 1) void b012q(
    const float* __restrict__ whh0,
    const float* __restrict__ wih1, const float* __restrict__ whh1,
    const float* __restrict__ bih1, const float* __restrict__ bhh1,
    const float* __restrict__ wih2, const float* __restrict__ whh2,
    const float* __restrict__ bih2, const float* __restrict__ bhh2,
    float* __restrict__ out)
{
    const int lane = threadIdx.x;
    const int gt   = lane & 3;
    const int b    = blockIdx.x * 8 + (lane >> 2);
    const int fsrc = (lane & ~3) | 1;            // f-lane of this quad

    const float W0 = __ldg(whh0 + gt);
    const float I1 = __ldg(wih1 + gt), H1 = __ldg(whh1 + gt);
    const float B1 = __ldg(bih1 + gt) + __ldg(bhh1 + gt);
    const float I2 = __ldg(wih2 + gt), H2 = __ldg(whh2 + gt);
    const float B2 = __ldg(bih2 + gt) + __ldg(bhh2 + gt);

    const bool istanh = (gt == 2);
    const float ca = istanh ? 2.f * L2E : -L2E;
    const float aa = istanh ? 1.f : 0.f;
    const float bm = istanh ? -2.f : 1.f;
    const bool isF = (gt == 1);

    const float* pb = reinterpret_cast<const float*>(g_pb0);
    float c0 = 0.f, c1 = 0.f, c2 = 0.f;
    float h0 = 0.f, h1 = 0.f, h2 = 0.f;

    // pregate prefetch (per-lane scalar, coalesced across warp)
    float p0 = __ldg(pb + ((size_t)0 * 256 + b) * 4 + gt);
    float p1 = __ldg(pb + ((size_t)1 * 256 + b) * 4 + gt);

#pragma unroll 1
    for (int tt = 0; tt < T_ + 2; ++tt) {
        float pn = (tt + 2 < T_) ? __ldg(pb + ((size_t)(tt + 2) * 256 + b) * 4 + gt) : 0.f;
        float in0 = h0, in1 = h1;

        if (tt < T_) {
            float v  = fmaf(W0, h0, p0);
            float r  = fmaf(bm, rcpa(1.f + ex2a(ca * v)), aa);
            float r2 = __shfl_xor_sync(0xffffffffu, r, 2);
            float r1 = __shfl_xor_sync(0xffffffffu, r * r2, 1);
            float cn = fmaf(r, c0, r1);
            float hn = r2 * tna(cn);
            if (isF) c0 = cn;
            h0 = __shfl_sync(0xffffffffu, hn, fsrc);
        }
        if (tt >= 1 && tt < T_ + 1) {
            float v  = fmaf(H1, h1, fmaf(I1, in0, B1));
            float r  = fmaf(bm, rcpa(1.f + ex2a(ca * v)), aa);
            float r2 = __shfl_xor_sync(0xffffffffu, r, 2);
            float r1 = __shfl_xor_sync(0xffffffffu, r * r2, 1);
            float cn = fmaf(r, c1, r1);
            float hn = r2 * tna(cn);
            if (isF) c1 = cn;
            h1 = __shfl_sync(0xffffffffu, hn, fsrc);
        }
        if (tt >= 2) {
            float v  = fmaf(H2, h2, fmaf(I2, in1, B2));
            float r  = fmaf(bm, rcpa(1.f + ex2a(ca * v)), aa);
            float r2 = __shfl_xor_sync(0xffffffffu, r, 2);
            float r1 = __shfl_xor_sync(0xffffffffu, r * r2, 1);
            float cn = fmaf(r, c2, r1);
            float hn = r2 * tna(cn);
            if (isF) c2 = cn;
            h2 = __shfl_sync(0xffffffffu, hn, fsrc);
            if (gt == 0) out[(size_t)b * T_ + (tt - 2)] = h2;
        }
        p0 = p1; p1 = pn;
    }
}

// ---------------------------------------------------------------------------
extern "C" void kernel_launch(void* const* d_in, const int* in_sizes, int n_in,
                              void* d_out, int out_size)
{
    const float* x = (const float*)d_in[0];
    const float *wih_a0 = (const float*)d_in[1],  *whh_a0 = (const float*)d_in[2];
    const float *bih_a0 = (const float*)d_in[3],  *bhh_a0 = (const float*)d_in[4];
    const float *wih_a1 = (const float*)d_in[5],  *whh_a1 = (const float*)d_in[6];
    const float *bih_a1 = (const float*)d_in[7],  *bhh_a1 = (const float*)d_in[8];
    const float *wih_a2 = (const float*)d_in[9],  *whh_a2 = (const float*)d_in[10];
    const float *bih_a2 = (const float*)d_in[11], *bhh_a2 = (const float*)d_in[12];
    const float *wih_b0 = (const float*)d_in[13], *whh_b0 = (const float*)d_in[14];
    const float *bih_b0 = (const float*)d_in[15], *bhh_b0 = (const float*)d_in[16];
    const float *wih_b1 = (const float*)d_in[17], *whh_b1 = (const float*)d_in[18];
    const float *bih_b1 = (const float*)d_in[19], *bhh_b1 = (const float*)d_in[20];
    const float *wih_b2 = (const float*)d_in[21], *whh_b2 = (const float*)d_in[22];
    const float *bih_b2 = (const float*)d_in[23], *bhh_b2 = (const float*)d_in[24];
    float* out = (float*)d_out;

    cudaFuncSetAttribute(fuseA, cudaFuncAttributeMaxDynamicSharedMemorySize,
                         SMEM_FUSE_BYTES);

    // fused a0+a1+a2 pipeline -> g_seqA
    fuseA<<<NPAIR, 256, SMEM_FUSE_BYTES>>>(
        x,
        wih_a0, whh_a0, bih_a0, bhh_a0,
        wih_a1, whh_a1, bih_a1, bhh_a1,
        wih_a2, whh_a2, bih_a2, bhh_a2);
    // b0 pre-gates from g_seqA
    preb0<<<512, 256>>>(wih_b0, bih_b0, bhh_b0);
    // b0/b1/b2 fused scalar recurrences (quad-gate) -> out
    b012q<<<32, 32>>>(whh_b0, wih_b1, whh_b1, bih_b1, bhh_b1,
                      wih_b2, whh_b2, bih_b2, bhh_b2, out);
}

// round 12
// speedup vs baseline: 1.0139x; 1.0139x over previous
#include <cuda_runtime.h>
#include <cstdint>

typedef unsigned long long u64;

#define B_    256
#define T_    512
#define NPAIR 128

// ---- device scratch (no allocations allowed) ------------------------------
__device__ __align__(16) float  g_seqA[(size_t)T_ * B_ * 64];   // 33.5 MB [t][b][64]
__device__ __align__(16) float4 g_pb0[(size_t)T_ * B_];         // 2 MB    [t*256+b]

// ---- packed f32x2 helpers -------------------------------------------------
__device__ __forceinline__ u64 pk2(float a, float b) {
    u64 r; asm("mov.b64 %0, {%1, %2};" : "=l"(r) : "f"(a), "f"(b)); return r;
}
__device__ __forceinline__ void unpk(u64 v, float& a, float& b) {
    asm("mov.b64 {%0, %1}, %2;" : "=f"(a), "=f"(b) : "l"(v));
}
__device__ __forceinline__ u64 ffma2(u64 a, u64 b, u64 c) {
    u64 d; asm("fma.rn.f32x2 %0, %1, %2, %3;" : "=l"(d) : "l"(a), "l"(b), "l"(c)); return d;
}

// ---- fast activations (MUFU ex2+rcp, ~1e-7 err) ---------------------------
#define L2E 1.4426950408889634f
__device__ __forceinline__ float ex2a(float x) {
    float r; asm("ex2.approx.ftz.f32 %0, %1;" : "=f"(r) : "f"(x)); return r;
}
__device__ __forceinline__ float rcpa(float x) {
    float r; asm("rcp.approx.ftz.f32 %0, %1;" : "=f"(r) : "f"(x)); return r;
}
__device__ __forceinline__ float sga(float x) { return rcpa(1.f + ex2a(-L2E * x)); }
__device__ __forceinline__ float tna(float x) {
    return fmaf(-2.f, rcpa(1.f + ex2a(2.f * L2E * x)), 1.f);
}

// ---- fused a0+a1+a2 pipeline: quad-gate lanes, ONE barrier/step ------------
// (byte-identical to round 10 — passing at 940us, protected)
#define SMEM_FUSE_BYTES 138240

__global__ __launch_bounds__(256, 1) void fuseA(
    const float* __restrict__ x,
    const float* __restrict__ wih_a0, const float* __restrict__ whh_a0,
    const float* __restrict__ bih_a0, const float* __restrict__ bhh_a0,
    const float* __restrict__ wih_a1, const float* __restrict__ whh_a1,
    const float* __restrict__ bih_a1, const float* __restrict__ bhh_a1,
    const float* __restrict__ wih_a2, const float* __restrict__ whh_a2,
    const float* __restrict__ bih_a2, const float* __restrict__ bhh_a2)
{
    extern __shared__ __align__(16) char smem[];
    ulonglong2* wT2 = reinterpret_cast<ulonglong2*>(smem);
    ulonglong2* wT3 = reinterpret_cast<ulonglong2*>(smem + 65536);
    float*  xs  = reinterpret_cast<float*>(smem + 131072);   // [2][512]
    float*  hs  = reinterpret_cast<float*>(smem + 135168);   // [2][3][2][64]

    const int tid  = threadIdx.x;
    const int lane = tid & 31, w = tid >> 5;
    const int gt   = lane & 3;                 // 0=i 1=f 2=g 3=o
    const int u    = w * 8 + (lane >> 2);      // unit 0..63
    const int gq   = gt * 64 + u;              // gate row index
    const bool isF = (gt == 1);
    const int pair = blockIdx.x;

    u64 wr0[32], wr1[32], wr2[32];
    {
        const u64* p0 = reinterpret_cast<const u64*>(whh_a0) + (size_t)gq * 32;
        const u64* p1 = reinterpret_cast<const u64*>(wih_a1) + (size_t)gq * 32;
        const u64* p2 = reinterpret_cast<const u64*>(whh_a1) + (size_t)gq * 32;
#pragma unroll
        for (int j = 0; j < 32; ++j) {
            wr0[j] = __ldg(p0 + j);
            wr1[j] = __ldg(p1 + j);
            wr2[j] = __ldg(p2 + j);
        }
    }
    {
        const ulonglong2* p2 = reinterpret_cast<const ulonglong2*>(wih_a2) + (size_t)gq * 16;
        const ulonglong2* p3 = reinterpret_cast<const ulonglong2*>(whh_a2) + (size_t)gq * 16;
#pragma unroll 4
        for (int i = 0; i < 16; ++i) {
            wT2[i * 256 + tid] = __ldg(p2 + i);
            wT3[i * 256 + tid] = __ldg(p3 + i);
        }
    }
#pragma unroll 2
    for (int k = 0; k < 4; ++k) {
        int i = tid + 256 * k, bl = i >> 9, t = i & 511;
        xs[bl * 512 + t] = x[(size_t)(pair * 2 + bl) * T_ + t];
    }
    if (tid < 128) {
#pragma unroll 2
        for (int q = 0; q < 6; ++q) hs[q * 128 + tid] = 0.f;
    }

    const float bias0 = __ldg(bih_a0 + gq) + __ldg(bhh_a0 + gq);
    const float bias1 = __ldg(bih_a1 + gq) + __ldg(bhh_a1 + gq);
    const float bias2 = __ldg(bih_a2 + gq) + __ldg(bhh_a2 + gq);
    const float wx0   = __ldg(wih_a0 + gq);

    const bool istanh = (gt == 2);
    const float ca = istanh ? 2.f * L2E : -L2E;
    const float aa = istanh ? 1.f : 0.f;
    const float bm = istanh ? -2.f : 1.f;

    float c0a = 0.f, c0b = 0.f, c1a = 0.f, c1b = 0.f, c2a = 0.f, c2b = 0.f;
    int p = 0;
    __syncthreads();

#pragma unroll 1
    for (int s = 0; s < T_ + 2; ++s) {
        const bool L0 = (s < T_);
        const bool L1 = (s >= 1) & (s < T_ + 1);
        const bool L2 = (s >= 2);
        const float* hb = hs + p * 384;
        float* hw = hs + (p ^ 1) * 384;

        float v0a = 0.f, v0b = 0.f, p1a = 0.f, p1b = 0.f;
        float h1a = 0.f, h1b = 0.f, p2a = 0.f, p2b = 0.f;
        float h2a = 0.f, h2b = 0.f;

        if (L0 | L1) {
            const ulonglong2* q0p = reinterpret_cast<const ulonglong2*>(hb + 0);
            const ulonglong2* q1p = reinterpret_cast<const ulonglong2*>(hb + 64);
            u64 ax = 0, bx = 0, ix = 0, jx = 0;
#pragma unroll
            for (int i = 0; i < 16; ++i) {
                ulonglong2 q0 = q0p[i], q1 = q1p[i];
                ax = ffma2(wr0[2 * i], q0.x, ax); ax = ffma2(wr0[2 * i + 1], q0.y, ax);
                bx = ffma2(wr0[2 * i], q1.x, bx); bx = ffma2(wr0[2 * i + 1], q1.y, bx);
                ix = ffma2(wr1[2 * i], q0.x, ix); ix = ffma2(wr1[2 * i + 1], q0.y, ix);
                jx = ffma2(wr1[2 * i], q1.x, jx); jx = ffma2(wr1[2 * i + 1], q1.y, jx);
            }
            float e, o;
            unpk(ax, e, o); v0a = e + o;
            unpk(bx, e, o); v0b = e + o;
            unpk(ix, e, o); p1a = e + o;
            unpk(jx, e, o); p1b = e + o;
        }
        if (L1 | L2) {
            const ulonglong2* q0p = reinterpret_cast<const ulonglong2*>(hb + 128);
            const ulonglong2* q1p = reinterpret_cast<const ulonglong2*>(hb + 192);
            u64 ax = 0, bx = 0, ix = 0, jx = 0;
#pragma unroll
            for (int i = 0; i < 16; ++i) {
                ulonglong2 q0 = q0p[i], q1 = q1p[i];
                ulonglong2 wv = wT2[i * 256 + tid];
                ax = ffma2(wr2[2 * i], q0.x, ax); ax = ffma2(wr2[2 * i + 1], q0.y, ax);
                bx = ffma2(wr2[2 * i], q1.x, bx); bx = ffma2(wr2[2 * i + 1], q1.y, bx);
                ix = ffma2(wv.x, q0.x, ix);       ix = ffma2(wv.y, q0.y, ix);
                jx = ffma2(wv.x, q1.x, jx);       jx = ffma2(wv.y, q1.y, jx);
            }
            float e, o;
            unpk(ax, e, o); h1a = e + o;
            unpk(bx, e, o); h1b = e + o;
            unpk(ix, e, o); p2a = e + o;
            unpk(jx, e, o); p2b = e + o;
        }
        if (L2) {
            const ulonglong2* q0p = reinterpret_cast<const ulonglong2*>(hb + 256);
            const ulonglong2* q1p = reinterpret_cast<const ulonglong2*>(hb + 320);
            u64 ax = 0, bx = 0;
#pragma unroll
            for (int i = 0; i < 16; ++i) {
                ulonglong2 q0 = q0p[i], q1 = q1p[i];
                ulonglong2 wv = wT3[i * 256 + tid];
                ax = ffma2(wv.x, q0.x, ax); ax = ffma2(wv.y, q0.y, ax);
                bx = ffma2(wv.x, q1.x, bx); bx = ffma2(wv.y, q1.y, bx);
            }
            float e, o;
            unpk(ax, e, o); h2a = e + o;
            unpk(bx, e, o); h2b = e + o;
        }

        if (L0) {
            float va = v0a + fmaf(wx0, xs[s], bias0);
            float vb = v0b + fmaf(wx0, xs[512 + s], bias0);
            float ra = fmaf(bm, rcpa(1.f + ex2a(ca * va)), aa);
            float rb = fmaf(bm, rcpa(1.f + ex2a(ca * vb)), aa);
            float r2a = __shfl_xor_sync(0xffffffffu, ra, 2);
            float r2b = __shfl_xor_sync(0xffffffffu, rb, 2);
            float r1a = __shfl_xor_sync(0xffffffffu, ra * r2a, 1);
            float r1b = __shfl_xor_sync(0xffffffffu, rb * r2b, 1);
            if (isF) {
                c0a = fmaf(ra, c0a, r1a);
                c0b = fmaf(rb, c0b, r1b);
                hw[u]      = r2a * tna(c0a);
                hw[64 + u] = r2b * tna(c0b);
            }
        }
        if (L1) {
            float va = h1a + p1a + bias1;
            float vb = h1b + p1b + bias1;
            float ra = fmaf(bm, rcpa(1.f + ex2a(ca * va)), aa);
            float rb = fmaf(bm, rcpa(1.f + ex2a(ca * vb)), aa);
            float r2a = __shfl_xor_sync(0xffffffffu, ra, 2);
            float r2b = __shfl_xor_sync(0xffffffffu, rb, 2);
            float r1a = __shfl_xor_sync(0xffffffffu, ra * r2a, 1);
            float r1b = __shfl_xor_sync(0xffffffffu, rb * r2b, 1);
            if (isF) {
                c1a = fmaf(ra, c1a, r1a);
                c1b = fmaf(rb, c1b, r1b);
                hw[128 + u] = r2a * tna(c1a);
                hw[192 + u] = r2b * tna(c1b);
            }
        }
        if (L2) {
            float va = h2a + p2a + bias2;
            float vb = h2b + p2b + bias2;
            float ra = fmaf(bm, rcpa(1.f + ex2a(ca * va)), aa);
            float rb = fmaf(bm, rcpa(1.f + ex2a(ca * vb)), aa);
            float r2a = __shfl_xor_sync(0xffffffffu, ra, 2);
            float r2b = __shfl_xor_sync(0xffffffffu, rb, 2);
            float r1a = __shfl_xor_sync(0xffffffffu, ra * r2a, 1);
            float r1b = __shfl_xor_sync(0xffffffffu, rb * r2b, 1);
            if (isF) {
                c2a = fmaf(ra, c2a, r1a);
                c2b = fmaf(rb, c2b, r1b);
                float ha = r2a * tna(c2a);
                float hb2 = r2b * tna(c2b);
                hw[256 + u] = ha;
                hw[320 + u] = hb2;
                g_seqA[((size_t)(s - 2) * B_ + pair * 2 + 0) * 64 + u] = ha;
                g_seqA[((size_t)(s - 2) * B_ + pair * 2 + 1) * 64 + u] = hb2;
            }
        }
        __syncthreads();
        p ^= 1;
    }
}

// ---------------------------------------------------------------------------
// b0 pre-gates: g_pb0[t*256+b] = bias_b0 + W_ih_b0[4,64] . seqA[t][b]
// 128-bit loads for 2x MLP.
// ---------------------------------------------------------------------------
__global__ __launch_bounds__(256, 1) void preb0(
    const float* __restrict__ w_ih, const float* __restrict__ b_ih,
    const float* __restrict__ b_hh)
{
    __shared__ ulonglong2 wsm2[64];   // 4 gates x 16 chunks
    __shared__ float bsm[4];
    const int tid = threadIdx.x;
    if (tid < 64) wsm2[tid] = __ldg(reinterpret_cast<const ulonglong2*>(w_ih) + tid);
    if (tid < 4) bsm[tid] = __ldg(b_ih + tid) + __ldg(b_hh + tid);
    __syncthreads();

    const size_t slot = (size_t)blockIdx.x * 256 + tid;  // = t*256 + b
    const ulonglong2* xp = reinterpret_cast<const ulonglong2*>(g_seqA) + slot * 16;
    u64 acc[4] = {0ull, 0ull, 0ull, 0ull};
#pragma unroll 4
    for (int j = 0; j < 16; ++j) {
        ulonglong2 xv = __ldg(xp + j);
#pragma unroll
        for (int gg = 0; gg < 4; ++gg) {
            ulonglong2 wv = wsm2[gg * 16 + j];
            acc[gg] = ffma2(wv.x, xv.x, acc[gg]);
            acc[gg] = ffma2(wv.y, xv.y, acc[gg]);
        }
    }
    float r[4];
#pragma unroll
    for (int gg = 0; gg < 4; ++gg) {
        float e, o; unpk(acc[gg], e, o);
        r[gg] = e + o + bsm[gg];
    }
    g_pb0[slot] = make_float4(r[0], r[1], r[2], r[3]);
}

// ---------------------------------------------------------------------------
// b0,b1,b2 scalar recurrences, LAYER-PER-WARP. 8 blocks x 96 threads.
// Warp 0: b0, warp 1: b1, warp 2: b2; each lane = one batch chain.
// h handoff via parity-double-buffered smem, ONE __syncthreads per iter.
// Iter k: b0@t=k, b1@t=k-1, b2@t=k-2.
// ---------------------------------------------------------------------------
__device__ __forceinline__ void step1(float4 pre, float4 whh, float& c, float& h) {
    float iv = sga(fmaf(whh.x, h, pre.x));
    float fv = sga(fmaf(whh.y, h, pre.y));
    float gv = tna(fmaf(whh.z, h, pre.z));
    float ov = sga(fmaf(whh.w, h, pre.w));
    c = fmaf(fv, c, iv * gv);
    h = ov * tna(c);
}

__global__ __launch_bounds__(96, 1) void b012p(
    const float* __restrict__ whh0,
    const float* __restrict__ wih1, const float* __restrict__ whh1,
    const float* __restrict__ bih1, const float* __restrict__ bhh1,
    const float* __restrict__ wih2, const float* __restrict__ whh2,
    const float* __restrict__ bih2, const float* __restrict__ bhh2,
    float* __restrict__ out)
{
    __shared__ float h01[2][32];   // b0 -> b1 handoff, [parity][lane]
    __shared__ float h12[2][32];   // b1 -> b2 handoff

    const int lane = threadIdx.x & 31;
    const int wp   = threadIdx.x >> 5;        // 0,1,2
    const int b    = blockIdx.x * 32 + lane;

    // per-warp params
    float4 WH, WI = make_float4(0.f, 0.f, 0.f, 0.f), BB = make_float4(0.f, 0.f, 0.f, 0.f);
    if (wp == 0) {
        WH = make_float4(__ldg(whh0 + 0), __ldg(whh0 + 1), __ldg(whh0 + 2), __ldg(whh0 + 3));
    } else if (wp == 1) {
        WH = make_float4(__ldg(whh1 + 0), __ldg(whh1 + 1), __ldg(whh1 + 2), __ldg(whh1 + 3));
        WI = make_float4(__ldg(wih1 + 0), __ldg(wih1 + 1), __ldg(wih1 + 2), __ldg(wih1 + 3));
        BB = make_float4(__ldg(bih1 + 0) + __ldg(bhh1 + 0), __ldg(bih1 + 1) + __ldg(bhh1 + 1),
                         __ldg(bih1 + 2) + __ldg(bhh1 + 2), __ldg(bih1 + 3) + __ldg(bhh1 + 3));
    } else {
        WH = make_float4(__ldg(whh2 + 0), __ldg(whh2 + 1), __ldg(whh2 + 2), __ldg(whh2 + 3));
        WI = make_float4(__ldg(wih2 + 0), __ldg(wih2 + 1), __ldg(wih2 + 2), __ldg(wih2 + 3));
        BB = make_float4(__ldg(bih2 + 0) + __ldg(bhh2 + 0), __ldg(bih2 + 1) + __ldg(bhh2 + 1),
                         __ldg(bih2 + 2) + __ldg(bhh2 + 2), __ldg(bih2 + 3) + __ldg(bhh2 + 3));
    }

    float c = 0.f, h = 0.f;
    // warp-0 pregate prefetch (depth 2)
    float4 p0 = make_float4(0.f, 0.f, 0.f, 0.f), p1 = p0;
    if (wp == 0) {
        p0 = g_pb0[b];
        p1 = g_pb0[256 + b];
    }
    if (wp == 0) { h01[0][lane] = 0.f; h01[1][lane] = 0.f; }
    if (wp == 1) { h12[0][lane] = 0.f; h12[1][lane] = 0.f; }
    __syncthreads();

#pragma unroll 1
    for (int k = 0; k < T_ + 2; ++k) {
        const int par = k & 1;
        if (wp == 0) {
            if (k < T_) {
                step1(p0, WH, c, h);
                h01[par ^ 1][lane] = h;
                p0 = p1;
                p1 = (k + 2 < T_) ? g_pb0[(size_t)(k + 2) * 256 + b]
                                  : make_float4(0.f, 0.f, 0.f, 0.f);
            }
        } else if (wp == 1) {
            if (k >= 1 && k < T_ + 1) {
                float hin = h01[par][lane];
                float4 pre = make_float4(fmaf(WI.x, hin, BB.x), fmaf(WI.y, hin, BB.y),
                                         fmaf(WI.z, hin, BB.z), fmaf(WI.w, hin, BB.w));
                step1(pre, WH, c, h);
                h12[par ^ 1][lane] = h;
            }
        } else {
            if (k >= 2) {
                float hin = h12[par][lane];
                float4 pre = make_float4(fmaf(WI.x, hin, BB.x), fmaf(WI.y, hin, BB.y),
                                         fmaf(WI.z, hin, BB.z), fmaf(WI.w, hin, BB.w));
                step1(pre, WH, c, h);
                out[(size_t)b * T_ + (k - 2)] = h;
            }
        }
        __syncthreads();
    }
}

// ---------------------------------------------------------------------------
extern "C" void kernel_launch(void* const* d_in, const int* in_sizes, int n_in,
                              void* d_out, int out_size)
{
    const float* x = (const float*)d_in[0];
    const float *wih_a0 = (const float*)d_in[1],  *whh_a0 = (const float*)d_in[2];
    const float *bih_a0 = (const float*)d_in[3],  *bhh_a0 = (const float*)d_in[4];
    const float *wih_a1 = (const float*)d_in[5],  *whh_a1 = (const float*)d_in[6];
    const float *bih_a1 = (const float*)d_in[7],  *bhh_a1 = (const float*)d_in[8];
    const float *wih_a2 = (const float*)d_in[9],  *whh_a2 = (const float*)d_in[10];
    const float *bih_a2 = (const float*)d_in[11], *bhh_a2 = (const float*)d_in[12];
    const float *wih_b0 = (const float*)d_in[13], *whh_b0 = (const float*)d_in[14];
    const float *bih_b0 = (const float*)d_in[15], *bhh_b0 = (const float*)d_in[16];
    const float *wih_b1 = (const float*)d_in[17], *whh_b1 = (const float*)d_in[18];
    const float *bih_b1 = (const float*)d_in[19], *bhh_b1 = (const float*)d_in[20];
    const float *wih_b2 = (const float*)d_in[21], *whh_b2 = (const float*)d_in[22];
    const float *bih_b2 = (const float*)d_in[23], *bhh_b2 = (const float*)d_in[24];
    float* out = (float*)d_out;

    cudaFuncSetAttribute(fuseA, cudaFuncAttributeMaxDynamicSharedMemorySize,
                         SMEM_FUSE_BYTES);

    // fused a0+a1+a2 pipeline -> g_seqA
    fuseA<<<NPAIR, 256, SMEM_FUSE_BYTES>>>(
        x,
        wih_a0, whh_a0, bih_a0, bhh_a0,
        wih_a1, whh_a1, bih_a1, bhh_a1,
        wih_a2, whh_a2, bih_a2, bhh_a2);
    // b0 pre-gates from g_seqA
    preb0<<<512, 256>>>(wih_b0, bih_b0, bhh_b0);
    // b0/b1/b2 recurrences, layer-per-warp -> out
    b012p<<<8, 96>>>(whh_b0, wih_b1, whh_b1, bih_b1, bhh_b1,
                     wih_b2, whh_b2, bih_b2, bhh_b2, out);
}